// round 4
// baseline (speedup 1.0000x reference)
#include <cuda_runtime.h>
#include <math.h>

#define BB 32
#define HH 32
#define KVHH 8
#define DD 128
#define GG 4
#define BLK_SZ 16
#define MAX_BLOCKS 128
#define NSPLIT2 32
#define NTHREADS 256   // 8 warps = 8 kvh heads

// Scratch (allocation-free: __device__ globals)
__device__ float g_pacc[BB * KVHH * NSPLIT2 * GG * DD];  // 16 MB
__device__ float g_pm[BB * KVHH * NSPLIT2 * GG];
__device__ float g_pl[BB * KVHH * NSPLIT2 * GG];
__device__ float g_qrot[BB * HH * DD];    // RoPE'd q, scale folded
__device__ float g_krot[BB * KVHH * DD];  // RoPE'd new k

// ---------------- prep: RoPE q and new-k once ----------------
__global__ __launch_bounds__(DD) void rope_prep_kernel(
    const float* __restrict__ query,
    const float* __restrict__ key,
    const int*   __restrict__ context_lens)
{
    const int b = blockIdx.x;
    const int h = blockIdx.y;   // 0..HH-1 q head, HH..HH+KVHH-1 k head
    const int d = threadIdx.x;

    const float pos = (float)context_lens[b];
    const int fi = d & 63;
    const float inv = exp2f(-(float)fi * 0.2076205092783674f);  // log2(10000)/64
    float s, c;
    sincosf(pos * inv, &s, &c);

    if (h < HH) {
        const float* base = query + ((long)b * HH + h) * DD;
        float x = base[d];
        float other = (d < 64) ? -base[d + 64] : base[d - 64];
        g_qrot[((long)b * HH + h) * DD + d] =
            (x * c + other * s) * 0.08838834764831845f;  // D^-0.5
    } else {
        const int kh = h - HH;
        const float* base = key + ((long)b * KVHH + kh) * DD;
        float x = base[d];
        float other = (d < 64) ? -base[d + 64] : base[d - 64];
        g_krot[((long)b * KVHH + kh) * DD + d] = x * c + other * s;
    }
}

// ---------------- per-token flash update (R2-proven path) ----------------
__device__ __forceinline__ void upd_token(
    const float4& kv, const float4& vv,
    const float4 qv[GG], float m[GG], float l[GG], float4 acc[GG])
{
    float sc[GG];
#pragma unroll
    for (int g = 0; g < GG; g++)
        sc[g] = kv.x * qv[g].x + kv.y * qv[g].y + kv.z * qv[g].z + kv.w * qv[g].w;
#pragma unroll
    for (int off = 16; off > 0; off >>= 1) {
#pragma unroll
        for (int g = 0; g < GG; g++)
            sc[g] += __shfl_xor_sync(0xffffffffu, sc[g], off);
    }
#pragma unroll
    for (int g = 0; g < GG; g++) {
        float mn = fmaxf(m[g], sc[g]);
        float alpha = __expf(m[g] - mn);
        float p = __expf(sc[g] - mn);
        l[g] = l[g] * alpha + p;
        acc[g].x = acc[g].x * alpha + p * vv.x;
        acc[g].y = acc[g].y * alpha + p * vv.y;
        acc[g].z = acc[g].z * alpha + p * vv.z;
        acc[g].w = acc[g].w * alpha + p * vv.w;
        m[g] = mn;
    }
}

// ---------------- split flash-decode: warp = kvh, CTA streams all heads ----------------
__global__ __launch_bounds__(NTHREADS) void pa_split_kernel(
    const float* __restrict__ value,
    const float* __restrict__ k_cache,
    const float* __restrict__ v_cache,
    const int*   __restrict__ block_table,
    const int*   __restrict__ context_lens)
{
    const int split = blockIdx.x;   // 0..NSPLIT2-1
    const int b     = blockIdx.y;
    const int tid   = threadIdx.x;
    const int lane  = tid & 31;
    const int kvh   = tid >> 5;     // warp index = kv head

    const int ctx   = context_lens[b];
    const int chunk = (ctx + NSPLIT2 - 1) / NSPLIT2;
    const int s0    = split * chunk;
    const int s1    = min(s0 + chunk, ctx);
    const int last  = ctx - 1;
    const int end   = min(s1, last);   // hot loop excludes in-flight token

    __shared__ int btab[MAX_BLOCKS];
    for (int i = tid; i < MAX_BLOCKS; i += NTHREADS)
        btab[i] = block_table[b * MAX_BLOCKS + i];
    __syncthreads();

    float4 qv[GG];
#pragma unroll
    for (int g = 0; g < GG; g++)
        qv[g] = *(const float4*)&g_qrot[((long)b * HH + kvh * GG + g) * DD + lane * 4];

    float m[GG], l[GG];
    float4 acc[GG];
#pragma unroll
    for (int g = 0; g < GG; g++) {
        m[g] = -1e30f; l[g] = 0.f;
        acc[g].x = acc[g].y = acc[g].z = acc[g].w = 0.f;
    }

    const unsigned hoff = (unsigned)kvh * DD + lane * 4;

    // warp advances token-sequentially; the 8 warps together cover the full
    // 4KB per token -> contiguous DRAM stream per CTA
    int s = s0;
    while (s + 3 < end) {
        unsigned o0 = (((unsigned)btab[(s    ) >> 4] * BLK_SZ + ((s    ) & 15)) * (KVHH * DD)) + hoff;
        unsigned o1 = (((unsigned)btab[(s + 1) >> 4] * BLK_SZ + ((s + 1) & 15)) * (KVHH * DD)) + hoff;
        unsigned o2 = (((unsigned)btab[(s + 2) >> 4] * BLK_SZ + ((s + 2) & 15)) * (KVHH * DD)) + hoff;
        unsigned o3 = (((unsigned)btab[(s + 3) >> 4] * BLK_SZ + ((s + 3) & 15)) * (KVHH * DD)) + hoff;

        float4 k0 = *(const float4*)(k_cache + o0);
        float4 v0 = *(const float4*)(v_cache + o0);
        float4 k1 = *(const float4*)(k_cache + o1);
        float4 v1 = *(const float4*)(v_cache + o1);
        float4 k2 = *(const float4*)(k_cache + o2);
        float4 v2 = *(const float4*)(v_cache + o2);
        float4 k3 = *(const float4*)(k_cache + o3);
        float4 v3 = *(const float4*)(v_cache + o3);

        upd_token(k0, v0, qv, m, l, acc);
        upd_token(k1, v1, qv, m, l, acc);
        upd_token(k2, v2, qv, m, l, acc);
        upd_token(k3, v3, qv, m, l, acc);
        s += 4;
    }
    while (s < end) {
        unsigned off = (((unsigned)btab[s >> 4] * BLK_SZ + (s & 15)) * (KVHH * DD)) + hoff;
        float4 kv = *(const float4*)(k_cache + off);
        float4 vv = *(const float4*)(v_cache + off);
        upd_token(kv, vv, qv, m, l, acc);
        s++;
    }

    // in-flight token (RoPE'd new k from scratch, new v from input)
    if (last >= s0 && last < s1) {
        float4 kv = *(const float4*)&g_krot[((long)b * KVHH + kvh) * DD + lane * 4];
        float4 vv = *(const float4*)(value + ((long)b * KVHH + kvh) * DD + lane * 4);
        upd_token(kv, vv, qv, m, l, acc);
    }

    // write partials directly (no cross-warp merge needed: warp owns its kvh)
    const long pbase = ((long)(b * KVHH + kvh) * NSPLIT2 + split) * GG;
#pragma unroll
    for (int g = 0; g < GG; g++)
        *(float4*)&g_pacc[(pbase + g) * DD + lane * 4] = acc[g];
    if (lane < GG) {
        g_pm[pbase + lane] = m[lane];
        g_pl[pbase + lane] = l[lane];
    }
}

// ---------------- combine ----------------
__global__ __launch_bounds__(DD) void pa_combine_kernel(float* __restrict__ out) {
    const int idx = blockIdx.x;             // B*KVH*G
    const int g   = idx % GG;
    const int kvh = (idx / GG) % KVHH;
    const int b   = idx / (GG * KVHH);
    const int d   = threadIdx.x;

    const long base = ((long)(b * KVHH + kvh) * NSPLIT2) * GG + g;
    float M = -1e30f;
#pragma unroll
    for (int s = 0; s < NSPLIT2; s++) M = fmaxf(M, g_pm[base + (long)s * GG]);
    float L = 0.f, o = 0.f;
#pragma unroll 8
    for (int s = 0; s < NSPLIT2; s++) {
        float f = __expf(g_pm[base + (long)s * GG] - M);
        L += f * g_pl[base + (long)s * GG];
        o += f * g_pacc[(base + (long)s * GG) * DD + d];
    }
    out[((long)b * HH + kvh * GG + g) * DD + d] = o / L;
}

extern "C" void kernel_launch(void* const* d_in, const int* in_sizes, int n_in,
                              void* d_out, int out_size) {
    const float* query  = (const float*)d_in[0];
    const float* key    = (const float*)d_in[1];
    const float* value  = (const float*)d_in[2];
    const float* k_cache = (const float*)d_in[3];
    const float* v_cache = (const float*)d_in[4];
    const int*   block_table  = (const int*)d_in[5];
    const int*   context_lens = (const int*)d_in[6];
    float* out = (float*)d_out;

    dim3 pgrid(BB, HH + KVHH);
    rope_prep_kernel<<<pgrid, DD>>>(query, key, context_lens);

    dim3 grid(NSPLIT2, BB);
    pa_split_kernel<<<grid, NTHREADS>>>(value, k_cache, v_cache,
                                        block_table, context_lens);
    pa_combine_kernel<<<BB * KVHH * GG, DD>>>(out);
}